// round 7
// baseline (speedup 1.0000x reference)
#include <cuda_runtime.h>
#include <cuda_bf16.h>

// Ball query: for each of NQ=32768 query points (p_grid), find first K=10
// points of x (NP=8192) with d2 <= RADIUS^2, ascending index order.
//
// Output buffer (float32), out_size = NQ*K + NQ*K*3:
//   [0 .. NQ*K)        mapping (index as float, 0 if not found)
//   [NQ*K .. NQ*K*4)   gathered coords (x[mapping], zeroed if not found)
//
// R7 = R6 (best: 16.9us) + dynamic work queue (batch=2) to kill the
// straggler tail from corner queries (scan ~2000 pts vs ~150 interior).
// Queue counters self-reset at kernel end (graph-replay safe).

#define NP 8192
#define NQ 32768
#define KNN 10
#define R2C 0.0625f
#define MAP_ELEMS (NQ * KNN)
#define NPC 2048            // points cached in SMEM (32 KB as float4)
#define WARPS_PER_CTA 8
#define WBATCH 2

__device__ unsigned g_work = 0;
__device__ unsigned g_done = 0;

__global__ void __launch_bounds__(256)
bq_kernel(const float* __restrict__ x,
          const float* __restrict__ pg,
          float* __restrict__ out)
{
    __shared__ float4 pts[NPC];                       // 32 KB
    __shared__ int scratch[WARPS_PER_CTA][16];        // hit indices (10 used)

    for (int i = threadIdx.x; i < NPC; i += blockDim.x) {
        const float px = x[3 * i + 0];
        const float py = x[3 * i + 1];
        const float pz = x[3 * i + 2];
        const float ps = px * px + py * py + pz * pz;
        pts[i] = make_float4(px, py, pz, ps);
    }
    __syncthreads();

    const int lane = threadIdx.x & 31;
    const int warp = threadIdx.x >> 5;
    const unsigned lt_mask = (1u << lane) - 1u;

    for (;;) {
        unsigned q0;
        if (lane == 0) q0 = atomicAdd(&g_work, WBATCH);
        q0 = __shfl_sync(0xffffffffu, q0, 0);
        if (q0 >= NQ) break;
        const unsigned qend = (q0 + WBATCH < NQ) ? q0 + WBATCH : NQ;

        for (unsigned q = q0; q < qend; q++) {
            const float qx = pg[3 * q + 0];
            const float qy = pg[3 * q + 1];
            const float qz = pg[3 * q + 2];
            const float q2 = qx * qx + qy * qy + qz * qz;

            int cnt = 0;

            // ---- phase 1: SMEM-cached prefix, 64 pts / iteration ----
            for (int base = 0; base < NPC; base += 64) {
                const float4 A = pts[base + lane];
                const float4 B = pts[base + 32 + lane];

                const float dotA = qx * A.x + qy * A.y + qz * A.z;
                const float d2A  = q2 + A.w - 2.0f * dotA;
                const float dotB = qx * B.x + qy * B.y + qz * B.z;
                const float d2B  = q2 + B.w - 2.0f * dotB;

                const bool vA = (d2A <= R2C);
                const bool vB = (d2B <= R2C);
                const unsigned mA = __ballot_sync(0xffffffffu, vA);
                const unsigned mB = __ballot_sync(0xffffffffu, vB);

                if (mA | mB) {    // warp-uniform: skip slot code on empty chunk
                    if (vA) {
                        const int slot = cnt + __popc(mA & lt_mask);
                        if (slot < KNN) scratch[warp][slot] = base + lane;
                    }
                    const int cA = cnt + __popc(mA);
                    if (vB) {
                        const int slot = cA + __popc(mB & lt_mask);
                        if (slot < KNN) scratch[warp][slot] = base + 32 + lane;
                    }
                    cnt = cA + __popc(mB);
                    if (cnt >= KNN) break;   // warp-uniform
                }
            }

            // ---- phase 2 (rare): tail from global, identical math ----
            if (cnt < KNN) {
                for (int base = NPC; base < NP; base += 32) {
                    const int i = base + lane;
                    const float px = x[3 * i + 0];
                    const float py = x[3 * i + 1];
                    const float pz = x[3 * i + 2];
                    const float ps  = px * px + py * py + pz * pz;
                    const float dot = qx * px + qy * py + qz * pz;
                    const float d2  = q2 + ps - 2.0f * dot;
                    const bool valid = (d2 <= R2C);
                    const unsigned mask = __ballot_sync(0xffffffffu, valid);
                    if (valid) {
                        const int slot = cnt + __popc(mask & lt_mask);
                        if (slot < KNN) scratch[warp][slot] = i;
                    }
                    cnt += __popc(mask);
                    if (cnt >= KNN) break;
                }
            }

            __syncwarp();   // make scratch STS visible to all lanes

            // ---- epilogue: lanes 0..9 emit mapping + coords ----
            const int c = cnt < KNN ? cnt : KNN;
            if (lane < KNN) {
                const bool found = (lane < c);
                const int idx = found ? scratch[warp][lane] : 0;
                out[(size_t)q * KNN + lane] = found ? (float)idx : 0.0f;

                float px = 0.0f, py = 0.0f, pz = 0.0f;
                if (found) {
                    if (idx < NPC) {
                        const float4 t = pts[idx];
                        px = t.x; py = t.y; pz = t.z;
                    } else {
                        px = x[3 * idx + 0];
                        py = x[3 * idx + 1];
                        pz = x[3 * idx + 2];
                    }
                }
                float* oc = out + MAP_ELEMS + ((size_t)q * KNN + lane) * 3;
                oc[0] = px; oc[1] = py; oc[2] = pz;
            }
            __syncwarp();   // scratch reuse safety for next query
        }
    }

    // ---- reset queue counters for next graph replay (last CTA) ----
    __syncthreads();
    if (threadIdx.x == 0) {
        const unsigned d = atomicAdd(&g_done, 1u);
        if (d == gridDim.x - 1) {
            atomicExch(&g_done, 0u);
            atomicExch(&g_work, 0u);
        }
    }
}

extern "C" void kernel_launch(void* const* d_in, const int* in_sizes, int n_in,
                              void* d_out, int out_size)
{
    const float* x  = (const float*)d_in[0];   // (1, 8192, 3)
    const float* pg = (const float*)d_in[1];   // (1, 64, 32, 16, 3)
    if (n_in >= 2 && in_sizes[0] == NQ * 3 && in_sizes[1] == NP * 3) {
        const float* t = x; x = pg; pg = t;
    }
    float* out = (float*)d_out;

    static bool attr_set = false;
    if (!attr_set) {
        cudaFuncSetAttribute(bq_kernel,
                             cudaFuncAttributePreferredSharedMemoryCarveout, 100);
        attr_set = true;
    }

    const int threads = 256;
    const int blocks  = 888;    // 6 CTAs/SM x 148 SMs = single wave

    bq_kernel<<<blocks, threads>>>(x, pg, out);
}

// round 12
// speedup vs baseline: 1.2578x; 1.2578x over previous
#include <cuda_runtime.h>
#include <cuda_bf16.h>

// Ball query: for each of NQ=32768 query points (p_grid), find first K=10
// points of x (NP=8192) with d2 <= RADIUS^2, ascending index order.
//
// Output buffer (float32), out_size = NQ*K + NQ*K*3:
//   [0 .. NQ*K)        mapping (index as float, 0 if not found)
//   [NQ*K .. NQ*K*4)   gathered coords (x[mapping], zeroed if not found)
//
// R9 = R6 (best: 16.9us) + 128-pt / 4-stream unroll, with the d2 expression
// kept TEXTUALLY identical to R6 (R8's fma reassociation flipped borderline
// validity bits -> mapping mismatch -> FAILED; never touch the math again).

#define NP 8192
#define NQ 32768
#define KNN 10
#define R2C 0.0625f
#define MAP_ELEMS (NQ * KNN)
#define NPC 2048            // points cached in SMEM (32 KB as float4)
#define WARPS_PER_CTA 8

__global__ void __launch_bounds__(256)
bq_kernel(const float* __restrict__ x,
          const float* __restrict__ pg,
          float* __restrict__ out)
{
    __shared__ float4 pts[NPC];                       // 32 KB
    __shared__ int scratch[WARPS_PER_CTA][16];        // hit indices (10 used)

    for (int i = threadIdx.x; i < NPC; i += blockDim.x) {
        const float px = x[3 * i + 0];
        const float py = x[3 * i + 1];
        const float pz = x[3 * i + 2];
        const float ps = px * px + py * py + pz * pz;
        pts[i] = make_float4(px, py, pz, ps);
    }
    __syncthreads();

    const int lane   = threadIdx.x & 31;
    const int warp   = threadIdx.x >> 5;
    const int gwarp  = (blockIdx.x * blockDim.x + threadIdx.x) >> 5;
    const int nwarps = (gridDim.x * blockDim.x) >> 5;
    const unsigned lt_mask = (1u << lane) - 1u;

    for (int q = gwarp; q < NQ; q += nwarps) {
        const float qx = pg[3 * q + 0];
        const float qy = pg[3 * q + 1];
        const float qz = pg[3 * q + 2];
        const float q2 = qx * qx + qy * qy + qz * qz;

        int cnt = 0;

        // ---- phase 1: SMEM-cached prefix, 128 pts / iter, 4 ILP streams ----
        // d2 expression identical to R6 for every stream.
        for (int base = 0; base < NPC; base += 128) {
            const float4 A = pts[base       + lane];
            const float4 B = pts[base + 32  + lane];
            const float4 C = pts[base + 64  + lane];
            const float4 D = pts[base + 96  + lane];

            const float dotA = qx * A.x + qy * A.y + qz * A.z;
            const float d2A  = q2 + A.w - 2.0f * dotA;
            const float dotB = qx * B.x + qy * B.y + qz * B.z;
            const float d2B  = q2 + B.w - 2.0f * dotB;
            const float dotC = qx * C.x + qy * C.y + qz * C.z;
            const float d2C  = q2 + C.w - 2.0f * dotC;
            const float dotD = qx * D.x + qy * D.y + qz * D.z;
            const float d2D  = q2 + D.w - 2.0f * dotD;

            const bool vA = (d2A <= R2C);
            const bool vB = (d2B <= R2C);
            const bool vC = (d2C <= R2C);
            const bool vD = (d2D <= R2C);
            const unsigned mA = __ballot_sync(0xffffffffu, vA);
            const unsigned mB = __ballot_sync(0xffffffffu, vB);
            const unsigned mC = __ballot_sync(0xffffffffu, vC);
            const unsigned mD = __ballot_sync(0xffffffffu, vD);

            if (mA | mB | mC | mD) {  // warp-uniform: skip on empty chunk
                if (vA) {
                    const int slot = cnt + __popc(mA & lt_mask);
                    if (slot < KNN) scratch[warp][slot] = base + lane;
                }
                const int cA = cnt + __popc(mA);
                if (vB) {
                    const int slot = cA + __popc(mB & lt_mask);
                    if (slot < KNN) scratch[warp][slot] = base + 32 + lane;
                }
                const int cB = cA + __popc(mB);
                if (vC) {
                    const int slot = cB + __popc(mC & lt_mask);
                    if (slot < KNN) scratch[warp][slot] = base + 64 + lane;
                }
                const int cC = cB + __popc(mC);
                if (vD) {
                    const int slot = cC + __popc(mD & lt_mask);
                    if (slot < KNN) scratch[warp][slot] = base + 96 + lane;
                }
                cnt = cC + __popc(mD);
                if (cnt >= KNN) break;   // warp-uniform
            }
        }

        // ---- phase 2 (rare): tail from global, identical math ----
        if (cnt < KNN) {
            for (int base = NPC; base < NP; base += 32) {
                const int i = base + lane;
                const float px = x[3 * i + 0];
                const float py = x[3 * i + 1];
                const float pz = x[3 * i + 2];
                const float ps  = px * px + py * py + pz * pz;
                const float dot = qx * px + qy * py + qz * pz;
                const float d2  = q2 + ps - 2.0f * dot;
                const bool valid = (d2 <= R2C);
                const unsigned mask = __ballot_sync(0xffffffffu, valid);
                if (valid) {
                    const int slot = cnt + __popc(mask & lt_mask);
                    if (slot < KNN) scratch[warp][slot] = i;
                }
                cnt += __popc(mask);
                if (cnt >= KNN) break;
            }
        }

        __syncwarp();   // make scratch STS visible to all lanes

        // ---- epilogue: lanes 0..9 emit mapping + coords ----
        const int c = cnt < KNN ? cnt : KNN;
        if (lane < KNN) {
            const bool found = (lane < c);
            const int idx = found ? scratch[warp][lane] : 0;
            out[(size_t)q * KNN + lane] = found ? (float)idx : 0.0f;

            float px = 0.0f, py = 0.0f, pz = 0.0f;
            if (found) {
                if (idx < NPC) {
                    const float4 t = pts[idx];
                    px = t.x; py = t.y; pz = t.z;
                } else {
                    px = x[3 * idx + 0];
                    py = x[3 * idx + 1];
                    pz = x[3 * idx + 2];
                }
            }
            float* oc = out + MAP_ELEMS + ((size_t)q * KNN + lane) * 3;
            oc[0] = px; oc[1] = py; oc[2] = pz;
        }
        __syncwarp();   // scratch reuse safety for next query
    }
}

extern "C" void kernel_launch(void* const* d_in, const int* in_sizes, int n_in,
                              void* d_out, int out_size)
{
    const float* x  = (const float*)d_in[0];   // (1, 8192, 3)
    const float* pg = (const float*)d_in[1];   // (1, 64, 32, 16, 3)
    if (n_in >= 2 && in_sizes[0] == NQ * 3 && in_sizes[1] == NP * 3) {
        const float* t = x; x = pg; pg = t;
    }
    float* out = (float*)d_out;

    static bool attr_set = false;
    if (!attr_set) {
        cudaFuncSetAttribute(bq_kernel,
                             cudaFuncAttributePreferredSharedMemoryCarveout, 100);
        attr_set = true;
    }

    const int threads = 256;
    const int blocks  = 888;    // 6 CTAs/SM x 148 SMs = single wave

    bq_kernel<<<blocks, threads>>>(x, pg, out);
}